// round 16
// baseline (speedup 1.0000x reference)
#include <cuda_runtime.h>
#include <cstdint>

// Problem constants
#define B 4
#define S 2048
#define D 1024
#define DS 64
#define TTT_LR 0.01f
#define LN_EPS 1e-5f
#define M_ROWS (B * S)

#define NC   64            // chunk length
#define NCH  (S / NC)      // 32 chunks
#define NCH2 (NCH / 2)     // 16 chunks per pipeline half
#define DSLA 32            // D-slice per pass-A CTA  (128 CTAs total)
#define DSLB 128           // D-slice per pass-B CTA

// Scratch (device globals)
__device__ float g_h[(size_t)B * S * D];            // layernormed input (tf32-rounded)
__device__ float g_wt[(size_t)D * D];               // Wv tf32-rounded
__device__ float g_v[(size_t)B * S * D];
__device__ float g_k[(size_t)B * S * DS];           // tf32-rounded
__device__ float g_q[(size_t)B * S * DS];           // tf32-rounded
__device__ float g_T [(size_t)B * NCH * NC * NC];   // (I + lr*trilKK)^-1, tf32-rounded
__device__ float g_Bq[(size_t)B * NCH * NC * NC];   // -lr*tril(QK^T,-1), tf32-rounded
__device__ float g_w [(size_t)B * NCH * D * DS];    // W snapshot (tf32-rounded)
__device__ float g_u [(size_t)B * NCH * NC * D];    // U per chunk (tf32-rounded)
__device__ float g_wst[(size_t)B * D * DS];         // fp32 W state between scanA parts

// ---------------------------------------------------------------------------
__device__ __forceinline__ float to_tf32(float x) {
    float r;
    asm("cvt.rna.tf32.f32 %0, %1;" : "=f"(r) : "f"(x));
    return r;
}
__device__ __forceinline__ void mma_m16n8k8_tf32(float c[4],
                                                 const uint32_t a[4],
                                                 uint32_t b0, uint32_t b1) {
    asm volatile(
        "mma.sync.aligned.m16n8k8.row.col.f32.tf32.tf32.f32 "
        "{%0,%1,%2,%3}, {%4,%5,%6,%7}, {%8,%9}, {%0,%1,%2,%3};\n"
        : "+f"(c[0]), "+f"(c[1]), "+f"(c[2]), "+f"(c[3])
        : "r"(a[0]), "r"(a[1]), "r"(a[2]), "r"(a[3]), "r"(b0), "r"(b1));
}
__device__ __forceinline__ void ldm_x4(uint32_t& r0, uint32_t& r1,
                                       uint32_t& r2, uint32_t& r3,
                                       uint32_t addr) {
    asm volatile("ldmatrix.sync.aligned.m8n8.x4.shared.b16 {%0,%1,%2,%3}, [%4];"
                 : "=r"(r0), "=r"(r1), "=r"(r2), "=r"(r3) : "r"(addr));
}
__device__ __forceinline__ void cp_async16(uint32_t dst, const float* src) {
    asm volatile("cp.async.cg.shared.global [%0], [%1], 16;\n"
                 :: "r"(dst), "l"(src));
}
#define CP_COMMIT() asm volatile("cp.async.commit_group;\n" ::: "memory")
#define CP_WAIT2()  asm volatile("cp.async.wait_group 2;\n" ::: "memory")
#define CP_WAIT1()  asm volatile("cp.async.wait_group 1;\n" ::: "memory")
#define CP_WAIT0()  asm volatile("cp.async.wait_group 0;\n" ::: "memory")

// ---------------------------------------------------------------------------
// Kernel 0: pre-round Wv to tf32
// ---------------------------------------------------------------------------
__global__ void cvtw_kernel(const float* __restrict__ Wv) {
    const int i = blockIdx.x * 256 + threadIdx.x;
    float4 v = ((const float4*)Wv)[i];
    v.x = to_tf32(v.x); v.y = to_tf32(v.y); v.z = to_tf32(v.z); v.w = to_tf32(v.w);
    ((float4*)g_wt)[i] = v;
}

// ---------------------------------------------------------------------------
// Kernel 1: LayerNorm — warp per row, 8 rows per CTA, no block barrier.
// ---------------------------------------------------------------------------
__global__ void __launch_bounds__(256)
ln_kernel(const float* __restrict__ x,
          const float* __restrict__ gamma,
          const float* __restrict__ beta) {
    const int wid  = threadIdx.x >> 5;
    const int lane = threadIdx.x & 31;
    const int row  = blockIdx.x * 8 + wid;

    const float4* xr = (const float4*)(x + (size_t)row * D);
    float4 v[8];
    float s = 0.f, ss = 0.f;
    #pragma unroll
    for (int i = 0; i < 8; i++) {
        v[i] = xr[i * 32 + lane];
        s  += v[i].x + v[i].y + v[i].z + v[i].w;
        ss += v[i].x * v[i].x + v[i].y * v[i].y + v[i].z * v[i].z + v[i].w * v[i].w;
    }
    #pragma unroll
    for (int o = 16; o > 0; o >>= 1) {
        s  += __shfl_xor_sync(0xFFFFFFFFu, s,  o);
        ss += __shfl_xor_sync(0xFFFFFFFFu, ss, o);
    }
    const float mu   = s * (1.0f / D);
    const float var  = ss * (1.0f / D) - mu * mu;
    const float rstd = rsqrtf(var + LN_EPS);

    float4* hr = (float4*)(g_h + (size_t)row * D);
    const float4* g4 = (const float4*)gamma;
    const float4* b4 = (const float4*)beta;
    #pragma unroll
    for (int i = 0; i < 8; i++) {
        const float4 g  = g4[i * 32 + lane];
        const float4 be = b4[i * 32 + lane];
        float4 h;
        h.x = to_tf32((v[i].x - mu) * rstd * g.x + be.x);
        h.y = to_tf32((v[i].y - mu) * rstd * g.y + be.y);
        h.z = to_tf32((v[i].z - mu) * rstd * g.z + be.z);
        h.w = to_tf32((v[i].w - mu) * rstd * g.w + be.w);
        hr[i * 32 + lane] = h;
    }
}

// ---------------------------------------------------------------------------
// Kernel 2a: Wv GEMM — cp.async 4-stage pipeline + ldmatrix fragments,
// 2 CTAs/SM. S-half version: toff selects t in [toff, toff+1024) per batch.
// grid = (32, 8): blockIdx.x -> (batch, block-within-half).
// ---------------------------------------------------------------------------
#define PBM 128
#define PBK 16
#define PST 20
#define NSTG 4
#define GEMMWV_SMEM (NSTG * 2 * PBM * PST * 4)   // 81920 B

__global__ void __launch_bounds__(256, 2)
gemm_wv_kernel(const float* __restrict__ A,
               const float* __restrict__ Wt,
               const float* __restrict__ bias,
               float* __restrict__ C,
               int toff) {
    extern __shared__ float smp[];
    const int bb = blockIdx.x >> 3;          // batch
    const int m0 = bb * S + toff + (blockIdx.x & 7) * PBM;
    const int n0 = blockIdx.y * PBM;

    const int tid  = threadIdx.x;
    const int wid  = tid >> 5;
    const int lane = tid & 31;
    const int wm   = wid & 3;
    const int wn   = wid >> 2;
    const int t    = lane & 3;

    const int rowA = tid >> 1;
    const int offA = (tid & 1) * 8;

    auto issue_stage = [&](int stg, int k0) {
        float* base = smp + stg * (2 * PBM * PST);
        float* bA = base;
        float* bW = base + PBM * PST;
        const float* srcA = &A[(size_t)(m0 + rowA) * 1024 + k0 + offA];
        const float* srcW = &Wt[(size_t)(n0 + rowA) * 1024 + k0 + offA];
        uint32_t dA = (uint32_t)__cvta_generic_to_shared(&bA[rowA * PST + offA]);
        uint32_t dW = (uint32_t)__cvta_generic_to_shared(&bW[rowA * PST + offA]);
        cp_async16(dA, srcA);
        cp_async16(dA + 16, srcA + 4);
        cp_async16(dW, srcW);
        cp_async16(dW + 16, srcW + 4);
        CP_COMMIT();
    };

    const int ltile = lane >> 3;
    const int lj    = lane & 7;
    uint32_t aoff[2], boff[4];
    #pragma unroll
    for (int tm = 0; tm < 2; tm++) {
        const int arow = wm * 32 + tm * 16 + (ltile & 1) * 8 + lj;
        const int acol = (ltile >> 1) * 4;
        aoff[tm] = (uint32_t)((arow * PST + acol) * 4);
    }
    #pragma unroll
    for (int gi = 0; gi < 4; gi++) {
        const int brow = wn * 64 + (gi * 2 + (ltile >> 1)) * 8 + lj;
        const int bcol = (ltile & 1) * 4;
        boff[gi] = (uint32_t)((PBM * PST + brow * PST + bcol) * 4);
    }
    const uint32_t sbase = (uint32_t)__cvta_generic_to_shared(smp);

    float acc[2][8][4];
    #pragma unroll
    for (int i = 0; i < 2; i++)
        #pragma unroll
        for (int j = 0; j < 8; j++)
            #pragma unroll
            for (int l = 0; l < 4; l++) acc[i][j][l] = 0.f;

    #pragma unroll
    for (int s = 0; s < NSTG - 1; s++) issue_stage(s, s * PBK);

    const int NIT = 1024 / PBK;   // 64
    for (int it = 0; it < NIT; it++) {
        if (it < NIT - 2)       { CP_WAIT2(); }
        else if (it == NIT - 2) { CP_WAIT1(); }
        else                    { CP_WAIT0(); }
        __syncthreads();

        const uint32_t stg = sbase + (uint32_t)((it & (NSTG - 1)) * (2 * PBM * PST) * 4);

        #pragma unroll
        for (int ks = 0; ks < 2; ks++) {
            const uint32_t kboff = (uint32_t)(ks * 8 * 4);
            uint32_t af[2][4];
            ldm_x4(af[0][0], af[0][1], af[0][2], af[0][3], stg + aoff[0] + kboff);
            ldm_x4(af[1][0], af[1][1], af[1][2], af[1][3], stg + aoff[1] + kboff);
            uint32_t bf[8][2];
            #pragma unroll
            for (int gi = 0; gi < 4; gi++) {
                ldm_x4(bf[gi * 2][0], bf[gi * 2][1],
                       bf[gi * 2 + 1][0], bf[gi * 2 + 1][1],
                       stg + boff[gi] + kboff);
            }
            #pragma unroll
            for (int tn = 0; tn < 8; tn++) {
                mma_m16n8k8_tf32(acc[0][tn], af[0], bf[tn][0], bf[tn][1]);
                mma_m16n8k8_tf32(acc[1][tn], af[1], bf[tn][0], bf[tn][1]);
            }
        }

        if (it + NSTG - 1 < NIT)
            issue_stage((it + NSTG - 1) & (NSTG - 1), (it + NSTG - 1) * PBK);
    }

    const int g = lane >> 2;
    #pragma unroll
    for (int tm = 0; tm < 2; tm++) {
        #pragma unroll
        for (int tn = 0; tn < 8; tn++) {
            const int gc   = n0 + wn * 64 + tn * 8 + 2 * t;
            const int row0 = m0 + wm * 32 + tm * 16 + g;
            const float bx = bias[gc];
            const float by = bias[gc + 1];
            float2 o0 = make_float2(acc[tm][tn][0] + bx, acc[tm][tn][1] + by);
            float2 o1 = make_float2(acc[tm][tn][2] + bx, acc[tm][tn][3] + by);
            *(float2*)&C[(size_t)row0 * D + gc] = o0;
            *(float2*)&C[(size_t)(row0 + 8) * D + gc] = o1;
        }
    }
}

// ---------------------------------------------------------------------------
// Kernel 2b: KQ GEMM — emits tf32-rounded k/q
// ---------------------------------------------------------------------------
#define GBM 128
#define GBK 16
#define SST 20
#define GK  1024

__global__ void __launch_bounds__(256, 1)
gemm_kq_kernel(const float* __restrict__ A,
               const float* __restrict__ W0,
               const float* __restrict__ W1,
               const float* __restrict__ bias0,
               const float* __restrict__ bias1,
               float* __restrict__ C0,
               float* __restrict__ C1) {
    __shared__ float sA[2][GBM * SST];
    __shared__ float sW[2][GBM * SST];

    const int tid  = threadIdx.x;
    const int m0   = blockIdx.x * GBM;
    const int wid  = tid >> 5;
    const int lane = tid & 31;
    const int wm   = wid & 3;
    const int wn   = wid >> 2;
    const int g    = lane >> 2;
    const int t    = lane & 3;
    const int lrow0 = tid >> 2;
    const int lcol  = (tid & 3) * 4;
    const int lrow1 = (tid + 256) >> 2;

    float4 aR[2], wR[2];
    auto load_tile = [&](int kk) {
        aR[0] = *(const float4*)&A[(size_t)(m0 + lrow0) * GK + kk + lcol];
        aR[1] = *(const float4*)&A[(size_t)(m0 + lrow1) * GK + kk + lcol];
        wR[0] = (lrow0 < 64)
            ? *(const float4*)&W0[(size_t)lrow0 * GK + kk + lcol]
            : *(const float4*)&W1[(size_t)(lrow0 - 64) * GK + kk + lcol];
        wR[1] = (lrow1 < 64)
            ? *(const float4*)&W0[(size_t)lrow1 * GK + kk + lcol]
            : *(const float4*)&W1[(size_t)(lrow1 - 64) * GK + kk + lcol];
    };
    auto store_tile = [&](int buf) {
        float4 a0 = aR[0], a1 = aR[1], w0 = wR[0], w1 = wR[1];
        w0.x = to_tf32(w0.x); w0.y = to_tf32(w0.y); w0.z = to_tf32(w0.z); w0.w = to_tf32(w0.w);
        w1.x = to_tf32(w1.x); w1.y = to_tf32(w1.y); w1.z = to_tf32(w1.z); w1.w = to_tf32(w1.w);
        *(float4*)&sA[buf][lrow0 * SST + lcol] = a0;
        *(float4*)&sA[buf][lrow1 * SST + lcol] = a1;
        *(float4*)&sW[buf][lrow0 * SST + lcol] = w0;
        *(float4*)&sW[buf][lrow1 * SST + lcol] = w1;
    };

    float acc[2][8][4];
    #pragma unroll
    for (int i = 0; i < 2; i++)
        #pragma unroll
        for (int j = 0; j < 8; j++)
            #pragma unroll
            for (int l = 0; l < 4; l++) acc[i][j][l] = 0.f;

    load_tile(0);
    store_tile(0);
    __syncthreads();

    const int NIT = GK / GBK;
    for (int it = 0; it < NIT; it++) {
        const int cur = it & 1;
        if (it + 1 < NIT) load_tile((it + 1) * GBK);
        #pragma unroll
        for (int ks = 0; ks < 2; ks++) {
            const int kb = ks * 8;
            uint32_t af[2][4];
            #pragma unroll
            for (int tm = 0; tm < 2; tm++) {
                const int r = wm * 32 + tm * 16 + g;
                af[tm][0] = __float_as_uint(sA[cur][r * SST + kb + t]);
                af[tm][1] = __float_as_uint(sA[cur][(r + 8) * SST + kb + t]);
                af[tm][2] = __float_as_uint(sA[cur][r * SST + kb + t + 4]);
                af[tm][3] = __float_as_uint(sA[cur][(r + 8) * SST + kb + t + 4]);
            }
            #pragma unroll
            for (int tn = 0; tn < 8; tn++) {
                const int n = wn * 64 + tn * 8 + g;
                const uint32_t b0 = __float_as_uint(sW[cur][n * SST + kb + t]);
                const uint32_t b1 = __float_as_uint(sW[cur][n * SST + kb + t + 4]);
                mma_m16n8k8_tf32(acc[0][tn], af[0], b0, b1);
                mma_m16n8k8_tf32(acc[1][tn], af[1], b0, b1);
            }
        }
        if (it + 1 < NIT) store_tile(cur ^ 1);
        __syncthreads();
    }

    #pragma unroll
    for (int tm = 0; tm < 2; tm++) {
        #pragma unroll
        for (int tn = 0; tn < 8; tn++) {
            const int colL = wn * 64 + tn * 8 + 2 * t;
            const int row0 = m0 + wm * 32 + tm * 16 + g;
            float* Cp = (colL < 64) ? C0 : C1;
            const int cc = colL & 63;
            const float bx = (colL < 64) ? bias0[cc] : bias1[cc];
            const float by = (colL < 64) ? bias0[cc + 1] : bias1[cc + 1];
            float2 o0 = make_float2(to_tf32(acc[tm][tn][0] + bx), to_tf32(acc[tm][tn][1] + by));
            float2 o1 = make_float2(to_tf32(acc[tm][tn][2] + bx), to_tf32(acc[tm][tn][3] + by));
            *(float2*)&Cp[(size_t)row0 * DS + cc] = o0;
            *(float2*)&Cp[(size_t)(row0 + 8) * DS + cc] = o1;
        }
    }
}

// ---------------------------------------------------------------------------
// Kernel 3: per-(b,chunk) precompute — emits tf32-rounded T / Bq
// ---------------------------------------------------------------------------
#define PREP_SMEM (4 * 64 * 68 * 4)

__global__ void __launch_bounds__(256)
prep_kernel() {
    extern __shared__ float sm[];
    float* sK = sm;
    float* sQ = sK + 64 * 68;
    float* sA = sQ + 64 * 68;
    float* sT = sA + 64 * 68;

    const int c = blockIdx.x, b = blockIdx.y;
    const int tid = threadIdx.x;
    const float* kg = g_k + ((size_t)b * S + c * NC) * DS;
    const float* qg = g_q + ((size_t)b * S + c * NC) * DS;

    for (int f = tid; f < NC * DS / 4; f += 256) {
        const int r = f >> 4, c4 = (f & 15) * 4;
        *(float4*)&sK[r * 68 + c4] = *(const float4*)&kg[r * DS + c4];
        *(float4*)&sQ[r * 68 + c4] = *(const float4*)&qg[r * DS + c4];
    }
    __syncthreads();

    float* Bg = g_Bq + ((size_t)(b * NCH + c)) * NC * NC;
    for (int e = tid; e < NC * NC; e += 256) {
        const int i = e >> 6, m = e & 63;
        float aK = 0.f, aQ = 0.f;
        #pragma unroll
        for (int kk = 0; kk < DS; kk += 4) {
            const float4 ki = *(const float4*)&sK[i * 68 + kk];
            const float4 qi = *(const float4*)&sQ[i * 68 + kk];
            const float4 km = *(const float4*)&sK[m * 68 + kk];
            aK += ki.x * km.x + ki.y * km.y + ki.z * km.z + ki.w * km.w;
            aQ += qi.x * km.x + qi.y * km.y + qi.z * km.z + qi.w * km.w;
        }
        sA[i * 68 + m] = (m < i) ? TTT_LR * aK : 0.f;
        Bg[e]          = (m < i) ? to_tf32(-TTT_LR * aQ) : 0.f;
    }
    __syncthreads();

    const int j = tid;
    if (j < NC) {
        for (int m = 0; m < NC; m++) sT[m * 68 + j] = (m == j) ? 1.f : 0.f;
    }
    __syncthreads();
    for (int i = 1; i < NC; i++) {
        if (j < i) {
            float s = 0.f;
            for (int m = 0; m < i; m++) s += sA[i * 68 + m] * sT[m * 68 + j];
            sT[i * 68 + j] = -s;
        }
        __syncthreads();
    }

    float* Tg = g_T + ((size_t)(b * NCH + c)) * NC * NC;
    for (int e = tid; e < NC * NC; e += 256)
        Tg[e] = to_tf32(sT[(e >> 6) * 68 + (e & 63)]);
}

// ---------------------------------------------------------------------------
// Kernel 4 (pass A): sequential state recurrence over chunk range [c0, c1).
// W state carried through g_wst (fp32) between parts. 128 CTAs.
// ---------------------------------------------------------------------------
#define CHUNK_FLTS (2 * 64 * 68 + 64 * 36)     // K + T + RV = 11008
#define SCANA_SMEM ((2 * 32 * 68 + 2 * CHUNK_FLTS + 64 * 36) * 4)

__global__ void __launch_bounds__(256, 1)
scan_state_kernel(int c0, int c1) {
    extern __shared__ float sm[];
    float* sW   = sm;                     // 32 x 68 fp32 master
    float* sWt  = sW + 32 * 68;           // 32 x 68 tf32 shadow
    float* sStg = sWt + 32 * 68;          // 2 x [K | T | RV]
    float* sU   = sStg + 2 * CHUNK_FLTS;  // 64 x 36 tf32

    const int b  = blockIdx.y;
    const int d0 = blockIdx.x * DSLA;
    const int tid  = threadIdx.x;
    const int wid  = tid >> 5;
    const int lane = tid & 31;
    const int g = lane >> 2, t = lane & 3;
    const int wm  = wid & 3;
    const int wn4 = wid >> 2;
    const int mb  = wm * 16, nb = wn4 * 16;
    const int wm2 = wid & 1;
    const int wn2 = wid >> 1;
    const int mb2 = wm2 * 16, nb2 = wn2 * 16;

    if (c0 == 0) {
        for (int i = tid; i < 32 * 68; i += 256) { sW[i] = 0.f; sWt[i] = 0.f; }
    } else {
        // restore fp32 state; rebuild tf32 shadow
        for (int f = tid; f < DSLA * DS / 4; f += 256) {
            const int dd = f >> 4, s4 = (f & 15) * 4;
            float4 w = *(const float4*)&g_wst[((size_t)b * D + d0 + dd) * DS + s4];
            *(float4*)&sW[dd * 68 + s4] = w;
            float4 wt = make_float4(to_tf32(w.x), to_tf32(w.y),
                                    to_tf32(w.z), to_tf32(w.w));
            *(float4*)&sWt[dd * 68 + s4] = wt;
        }
    }

    auto stage_chunk = [&](int c, int buf) {
        float* bK  = sStg + buf * CHUNK_FLTS;
        float* bT  = bK + 64 * 68;
        float* bRV = bT + 64 * 68;
        const float* kg = g_k + ((size_t)b * S + c * NC) * DS;
        const float* Tg = g_T + ((size_t)(b * NCH + c)) * NC * NC;
        #pragma unroll
        for (int f = tid; f < 1024; f += 256) {
            const int r = f >> 4, c4 = (f & 15) * 4;
            cp_async16((uint32_t)__cvta_generic_to_shared(&bK[r * 68 + c4]),
                       &kg[r * DS + c4]);
            cp_async16((uint32_t)__cvta_generic_to_shared(&bT[r * 68 + c4]),
                       &Tg[r * 64 + c4]);
        }
        #pragma unroll
        for (int f = tid; f < 512; f += 256) {
            const int r = f >> 3, c4 = (f & 7) * 4;
            cp_async16((uint32_t)__cvta_generic_to_shared(&bRV[r * 36 + c4]),
                       &g_v[((size_t)(b * S) + c * NC + r) * D + d0 + c4]);
        }
        CP_COMMIT();
    };

    stage_chunk(c0, 0);
    int buf = 0;

    for (int c = c0; c < c1; c++) {
        if (c + 1 < c1) { stage_chunk(c + 1, buf ^ 1); CP_WAIT1(); }
        else            { CP_WAIT0(); }
        __syncthreads();

        float* bK  = sStg + buf * CHUNK_FLTS;
        float* bT  = bK + 64 * 68;
        float* bRV = bT + 64 * 68;

        // snapshot W (tf32 shadow) -> g_w
        #pragma unroll
        for (int f = tid; f < DSLA * DS / 4; f += 256) {
            const int dd = f >> 4, s4 = (f & 15) * 4;
            *(float4*)&g_w[((size_t)(b * NCH + c) * D + d0 + dd) * DS + s4] =
                *(const float4*)&sWt[dd * 68 + s4];
        }

        // GEMM1: R = K W^T - V
        {
            float acc[2][4] = {};
            #pragma unroll
            for (int ks = 0; ks < 8; ks++) {
                const int k0 = ks * 8;
                uint32_t a[4];
                a[0] = __float_as_uint(bK[(mb + g) * 68 + k0 + t]);
                a[1] = __float_as_uint(bK[(mb + g + 8) * 68 + k0 + t]);
                a[2] = __float_as_uint(bK[(mb + g) * 68 + k0 + t + 4]);
                a[3] = __float_as_uint(bK[(mb + g + 8) * 68 + k0 + t + 4]);
                #pragma unroll
                for (int tn = 0; tn < 2; tn++) {
                    const int n = nb + tn * 8 + g;
                    const uint32_t b0 = __float_as_uint(sWt[n * 68 + k0 + t]);
                    const uint32_t b1 = __float_as_uint(sWt[n * 68 + k0 + t + 4]);
                    mma_m16n8k8_tf32(acc[tn], a, b0, b1);
                }
            }
            #pragma unroll
            for (int tn = 0; tn < 2; tn++) {
                const int cc = nb + tn * 8 + 2 * t;
                float2 v0 = *(float2*)&bRV[(mb + g) * 36 + cc];
                float2 v1 = *(float2*)&bRV[(mb + g + 8) * 36 + cc];
                *(float2*)&bRV[(mb + g) * 36 + cc] =
                    make_float2(acc[tn][0] - v0.x, acc[tn][1] - v0.y);
                *(float2*)&bRV[(mb + g + 8) * 36 + cc] =
                    make_float2(acc[tn][2] - v1.x, acc[tn][3] - v1.y);
            }
        }
        __syncthreads();

        // GEMM2: U = T R
        {
            float acc[2][4] = {};
            #pragma unroll
            for (int ks = 0; ks < 8; ks++) {
                const int k0 = ks * 8;
                uint32_t a[4];
                a[0] = __float_as_uint(bT[(mb + g) * 68 + k0 + t]);
                a[1] = __float_as_uint(bT[(mb + g + 8) * 68 + k0 + t]);
                a[2] = __float_as_uint(bT[(mb + g) * 68 + k0 + t + 4]);
                a[3] = __float_as_uint(bT[(mb + g + 8) * 68 + k0 + t + 4]);
                #pragma unroll
                for (int tn = 0; tn < 2; tn++) {
                    const int n = nb + tn * 8 + g;
                    const uint32_t b0 = __float_as_uint(to_tf32(bRV[(k0 + t) * 36 + n]));
                    const uint32_t b1 = __float_as_uint(to_tf32(bRV[(k0 + t + 4) * 36 + n]));
                    mma_m16n8k8_tf32(acc[tn], a, b0, b1);
                }
            }
            #pragma unroll
            for (int tn = 0; tn < 2; tn++) {
                const int cc = nb + tn * 8 + 2 * t;
                float2 u0 = make_float2(to_tf32(acc[tn][0]), to_tf32(acc[tn][1]));
                float2 u1 = make_float2(to_tf32(acc[tn][2]), to_tf32(acc[tn][3]));
                *(float2*)&sU[(mb + g) * 36 + cc]     = u0;
                *(float2*)&sU[(mb + g + 8) * 36 + cc] = u1;
                *(float2*)&g_u[((size_t)(b * NCH + c) * NC + mb + g) * D + d0 + cc]     = u0;
                *(float2*)&g_u[((size_t)(b * NCH + c) * NC + mb + g + 8) * D + d0 + cc] = u1;
            }
        }
        __syncthreads();

        // GEMM4: dW = U^T K + W update
        {
            float acc4[2][4] = {};
            #pragma unroll
            for (int ks = 0; ks < 8; ks++) {
                const int k0 = ks * 8;
                uint32_t a[4];
                a[0] = __float_as_uint(sU[(k0 + t) * 36 + mb2 + g]);
                a[1] = __float_as_uint(sU[(k0 + t) * 36 + mb2 + g + 8]);
                a[2] = __float_as_uint(sU[(k0 + t + 4) * 36 + mb2 + g]);
                a[3] = __float_as_uint(sU[(k0 + t + 4) * 36 + mb2 + g + 8]);
                #pragma unroll
                for (int tn = 0; tn < 2; tn++) {
                    const int n = nb2 + tn * 8 + g;
                    const uint32_t b0 = __float_as_uint(bK[(k0 + t) * 68 + n]);
                    const uint32_t b1 = __float_as_uint(bK[(k0 + t + 4) * 68 + n]);
                    mma_m16n8k8_tf32(acc4[tn], a, b0, b1);
                }
            }
            #pragma unroll
            for (int tn = 0; tn < 2; tn++) {
                const int ss = nb2 + tn * 8 + 2 * t;
                float2 w0 = *(float2*)&sW[(mb2 + g) * 68 + ss];
                float2 w1 = *(float2*)&sW[(mb2 + g + 8) * 68 + ss];
                w0.x -= TTT_LR * acc4[tn][0]; w0.y -= TTT_LR * acc4[tn][1];
                w1.x -= TTT_LR * acc4[tn][2]; w1.y -= TTT_LR * acc4[tn][3];
                *(float2*)&sW[(mb2 + g) * 68 + ss] = w0;
                *(float2*)&sW[(mb2 + g + 8) * 68 + ss] = w1;
                *(float2*)&sWt[(mb2 + g) * 68 + ss] =
                    make_float2(to_tf32(w0.x), to_tf32(w0.y));
                *(float2*)&sWt[(mb2 + g + 8) * 68 + ss] =
                    make_float2(to_tf32(w1.x), to_tf32(w1.y));
            }
        }
        __syncthreads();
        buf ^= 1;
    }

    // persist fp32 state for the next part
    if (c1 < NCH) {
        for (int f = tid; f < DSLA * DS / 4; f += 256) {
            const int dd = f >> 4, s4 = (f & 15) * 4;
            *(float4*)&g_wst[((size_t)b * D + d0 + dd) * DS + s4] =
                *(const float4*)&sW[dd * 68 + s4];
        }
    }
}

// ---------------------------------------------------------------------------
// Kernel 5 (pass B): fully parallel output computation over chunk range.
// ---------------------------------------------------------------------------
#define SCANB_SMEM ((2 * 64 * 68 + 128 * 68 + 64 * 132) * 4)

__global__ void __launch_bounds__(256, 1)
scan_y_kernel(const float* __restrict__ x, float* __restrict__ out, int cbase) {
    extern __shared__ float sm[];
    float* sQ = sm;
    float* sB = sQ + 64 * 68;
    float* sW = sB + 64 * 68;
    float* sU = sW + 128 * 68;

    const int b  = blockIdx.z;
    const int c  = cbase + blockIdx.y;
    const int d0 = blockIdx.x * DSLB;
    const int t0 = c * NC;
    const int tid  = threadIdx.x;
    const int wid  = tid >> 5;
    const int lane = tid & 31;
    const int g = lane >> 2, t = lane & 3;
    const int wm = wid & 3, wn = wid >> 2;
    const int mb = wm * 16, nbv = wn * 64;

    const float* qg = g_q  + ((size_t)b * S + t0) * DS;
    const float* Bg = g_Bq + ((size_t)(b * NCH + c)) * NC * NC;
    #pragma unroll
    for (int f = tid; f < NC * DS / 4; f += 256) {
        const int r = f >> 4, c4 = (f & 15) * 4;
        *(float4*)&sQ[r * 68 + c4] = *(const float4*)&qg[r * DS + c4];
        *(float4*)&sB[r * 68 + c4] = *(const float4*)&Bg[r * 64 + c4];
    }
    const float* wg = g_w + ((size_t)(b * NCH + c) * D + d0) * DS;
    #pragma unroll
    for (int f = tid; f < DSLB * DS / 4; f += 256) {
        const int r = f >> 4, c4 = (f & 15) * 4;
        *(float4*)&sW[r * 68 + c4] = *(const float4*)&wg[(size_t)r * DS + c4];
    }
    const float* ug = g_u + ((size_t)(b * NCH + c)) * NC * D + d0;
    #pragma unroll
    for (int f = tid; f < NC * DSLB / 4; f += 256) {
        const int r = f >> 5, c4 = (f & 31) * 4;
        *(float4*)&sU[r * 132 + c4] = *(const float4*)&ug[(size_t)r * D + c4];
    }
    __syncthreads();

    float acc[8][4] = {};
    #pragma unroll
    for (int ks = 0; ks < 8; ks++) {
        const int k0 = ks * 8;
        uint32_t a[4];
        a[0] = __float_as_uint(sQ[(mb + g) * 68 + k0 + t]);
        a[1] = __float_as_uint(sQ[(mb + g + 8) * 68 + k0 + t]);
        a[2] = __float_as_uint(sQ[(mb + g) * 68 + k0 + t + 4]);
        a[3] = __float_as_uint(sQ[(mb + g + 8) * 68 + k0 + t + 4]);
        #pragma unroll
        for (int tn = 0; tn < 8; tn++) {
            const int n = nbv + tn * 8 + g;
            const uint32_t b0 = __float_as_uint(sW[n * 68 + k0 + t]);
            const uint32_t b1 = __float_as_uint(sW[n * 68 + k0 + t + 4]);
            mma_m16n8k8_tf32(acc[tn], a, b0, b1);
        }
    }
    #pragma unroll
    for (int ks = 0; ks < 8; ks++) {
        const int k0 = ks * 8;
        uint32_t a[4];
        a[0] = __float_as_uint(sB[(mb + g) * 68 + k0 + t]);
        a[1] = __float_as_uint(sB[(mb + g + 8) * 68 + k0 + t]);
        a[2] = __float_as_uint(sB[(mb + g) * 68 + k0 + t + 4]);
        a[3] = __float_as_uint(sB[(mb + g + 8) * 68 + k0 + t + 4]);
        #pragma unroll
        for (int tn = 0; tn < 8; tn++) {
            const int n = nbv + tn * 8 + g;
            const uint32_t b0 = __float_as_uint(sU[(k0 + t) * 132 + n]);
            const uint32_t b1 = __float_as_uint(sU[(k0 + t + 4) * 132 + n]);
            mma_m16n8k8_tf32(acc[tn], a, b0, b1);
        }
    }
    #pragma unroll
    for (int tn = 0; tn < 8; tn++) {
        const int dc = d0 + nbv + tn * 8 + 2 * t;
        const size_t o0 = ((size_t)b * S + t0 + mb + g) * D + dc;
        const size_t o1 = ((size_t)b * S + t0 + mb + g + 8) * D + dc;
        const float2 x0 = *(const float2*)&x[o0];
        const float2 x1 = *(const float2*)&x[o1];
        *(float2*)&out[o0] = make_float2(x0.x + acc[tn][0], x0.y + acc[tn][1]);
        *(float2*)&out[o1] = make_float2(x1.x + acc[tn][2], x1.y + acc[tn][3]);
    }
}

// ---------------------------------------------------------------------------
// Launch — chunk-pipelined schedule:
//   s1:   cvtw | Wv(half1) ─ evWv1 ─ Wv(half2) ─ evWv2     scanB(0-15) ─ evB1
//   main: ln ─ evLN        | kq, prep | wait evWv1 scanA(0-16) ─ evA1
//         wait evWv2 scanA(16-32) | wait evB1 scanB(16-32)
// ---------------------------------------------------------------------------
extern "C" void kernel_launch(void* const* d_in, const int* in_sizes, int n_in,
                              void* d_out, int out_size) {
    const float* x     = (const float*)d_in[0];
    const float* Wk    = (const float*)d_in[1];
    const float* bk    = (const float*)d_in[2];
    const float* Wv    = (const float*)d_in[3];
    const float* bv    = (const float*)d_in[4];
    const float* Wq    = (const float*)d_in[5];
    const float* bq    = (const float*)d_in[6];
    const float* gamma = (const float*)d_in[7];
    const float* beta  = (const float*)d_in[8];
    float* out = (float*)d_out;

    float* hptr;  cudaGetSymbolAddress((void**)&hptr, g_h);
    float* wtptr; cudaGetSymbolAddress((void**)&wtptr, g_wt);
    float* vptr;  cudaGetSymbolAddress((void**)&vptr, g_v);
    float* kptr;  cudaGetSymbolAddress((void**)&kptr, g_k);
    float* qptr;  cudaGetSymbolAddress((void**)&qptr, g_q);

    static cudaStream_t s1 = nullptr;
    static cudaEvent_t ev0 = nullptr, evLN = nullptr, evWv1 = nullptr,
                       evWv2 = nullptr, evA1 = nullptr, evB1 = nullptr;
    static bool attrs_set = false;
    if (!s1) {
        cudaStreamCreateWithFlags(&s1, cudaStreamNonBlocking);
        cudaEventCreateWithFlags(&ev0,   cudaEventDisableTiming);
        cudaEventCreateWithFlags(&evLN,  cudaEventDisableTiming);
        cudaEventCreateWithFlags(&evWv1, cudaEventDisableTiming);
        cudaEventCreateWithFlags(&evWv2, cudaEventDisableTiming);
        cudaEventCreateWithFlags(&evA1,  cudaEventDisableTiming);
        cudaEventCreateWithFlags(&evB1,  cudaEventDisableTiming);
    }
    if (!attrs_set) {
        cudaFuncSetAttribute(gemm_wv_kernel,
                             cudaFuncAttributeMaxDynamicSharedMemorySize, GEMMWV_SMEM);
        cudaFuncSetAttribute(prep_kernel,
                             cudaFuncAttributeMaxDynamicSharedMemorySize, PREP_SMEM);
        cudaFuncSetAttribute(scan_state_kernel,
                             cudaFuncAttributeMaxDynamicSharedMemorySize, SCANA_SMEM);
        cudaFuncSetAttribute(scan_y_kernel,
                             cudaFuncAttributeMaxDynamicSharedMemorySize, SCANB_SMEM);
        attrs_set = true;
    }

    // Fork side stream off the main (possibly capturing) stream.
    cudaEventRecord(ev0, 0);
    cudaStreamWaitEvent(s1, ev0, 0);

    // s1: pre-round Wv (independent of LN)
    cvtw_kernel<<<(D * D / 4) / 256, 256, 0, s1>>>(Wv);

    // main: LayerNorm (warp per row)
    ln_kernel<<<M_ROWS / 8, 256>>>(x, gamma, beta);
    cudaEventRecord(evLN, 0);

    // s1: Wv GEMM in two S-halves (needs LN + cvtw)
    cudaStreamWaitEvent(s1, evLN, 0);
    gemm_wv_kernel<<<dim3(32, D / PBM), 256, GEMMWV_SMEM, s1>>>(
        hptr, wtptr, bv, vptr, 0);
    cudaEventRecord(evWv1, s1);
    gemm_wv_kernel<<<dim3(32, D / PBM), 256, GEMMWV_SMEM, s1>>>(
        hptr, wtptr, bv, vptr, S / 2);
    cudaEventRecord(evWv2, s1);

    // main (concurrent with Wv GEMM): KQ projection + prep (all chunks)
    gemm_kq_kernel<<<dim3(M_ROWS / GBM, 1), 256>>>(
        hptr, Wk, Wq, bk, bq, kptr, qptr);
    prep_kernel<<<dim3(NCH, B), 256, PREP_SMEM>>>();

    // Pass A part 1: chunks [0,16)  (needs g_v first half + k/T)
    cudaStreamWaitEvent(0, evWv1, 0);
    scan_state_kernel<<<dim3(D / DSLA, B), 256, SCANA_SMEM>>>(0, NCH2);
    cudaEventRecord(evA1, 0);

    // s1: Pass B part 1 (chunks [0,16)) — overlaps pass A part 2
    cudaStreamWaitEvent(s1, evA1, 0);
    scan_y_kernel<<<dim3(D / DSLB, NCH2, B), 256, SCANB_SMEM, s1>>>(x, out, 0);
    cudaEventRecord(evB1, s1);

    // main: Pass A part 2: chunks [16,32)  (needs g_v second half)
    cudaStreamWaitEvent(0, evWv2, 0);
    scan_state_kernel<<<dim3(D / DSLA, B), 256, SCANA_SMEM>>>(NCH2, NCH);

    // main: Pass B part 2 (joins scanB part 1 so the graph completes correctly)
    cudaStreamWaitEvent(0, evB1, 0);
    scan_y_kernel<<<dim3(D / DSLB, NCH2, B), 256, SCANB_SMEM>>>(x, out, NCH2);
}

// round 17
// speedup vs baseline: 1.3529x; 1.3529x over previous
#include <cuda_runtime.h>
#include <cstdint>

// Problem constants
#define B 4
#define S 2048
#define D 1024
#define DS 64
#define TTT_LR 0.01f
#define LN_EPS 1e-5f
#define M_ROWS (B * S)

#define NC   64            // chunk length
#define NCH  (S / NC)      // 32 chunks
#define DSLA 32            // D-slice per pass-A CTA  (128 CTAs total)
#define DSLB 128           // D-slice per pass-B CTA

// Scratch (device globals)
__device__ float g_h[(size_t)B * S * D];            // layernormed input (tf32-rounded)
__device__ float g_wt[(size_t)D * D];               // Wv tf32-rounded
__device__ float g_v[(size_t)B * S * D];
__device__ float g_k[(size_t)B * S * DS];           // tf32-rounded
__device__ float g_q[(size_t)B * S * DS];           // tf32-rounded
__device__ float g_T [(size_t)B * NCH * NC * NC];   // (I + lr*trilKK)^-1, tf32-rounded
__device__ float g_Bq[(size_t)B * NCH * NC * NC];   // -lr*tril(QK^T,-1), tf32-rounded
__device__ float g_w [(size_t)B * NCH * D * DS];    // W snapshot (tf32-rounded)
__device__ float g_u [(size_t)B * NCH * NC * D];    // U per chunk (tf32-rounded)

// ---------------------------------------------------------------------------
__device__ __forceinline__ float to_tf32(float x) {
    float r;
    asm("cvt.rna.tf32.f32 %0, %1;" : "=f"(r) : "f"(x));
    return r;
}
__device__ __forceinline__ void mma_m16n8k8_tf32(float c[4],
                                                 const uint32_t a[4],
                                                 uint32_t b0, uint32_t b1) {
    asm volatile(
        "mma.sync.aligned.m16n8k8.row.col.f32.tf32.tf32.f32 "
        "{%0,%1,%2,%3}, {%4,%5,%6,%7}, {%8,%9}, {%0,%1,%2,%3};\n"
        : "+f"(c[0]), "+f"(c[1]), "+f"(c[2]), "+f"(c[3])
        : "r"(a[0]), "r"(a[1]), "r"(a[2]), "r"(a[3]), "r"(b0), "r"(b1));
}
__device__ __forceinline__ void ldm_x4(uint32_t& r0, uint32_t& r1,
                                       uint32_t& r2, uint32_t& r3,
                                       uint32_t addr) {
    asm volatile("ldmatrix.sync.aligned.m8n8.x4.shared.b16 {%0,%1,%2,%3}, [%4];"
                 : "=r"(r0), "=r"(r1), "=r"(r2), "=r"(r3) : "r"(addr));
}
__device__ __forceinline__ void cp_async16(uint32_t dst, const float* src) {
    asm volatile("cp.async.cg.shared.global [%0], [%1], 16;\n"
                 :: "r"(dst), "l"(src));
}
#define CP_COMMIT() asm volatile("cp.async.commit_group;\n" ::: "memory")
#define CP_WAIT2()  asm volatile("cp.async.wait_group 2;\n" ::: "memory")
#define CP_WAIT1()  asm volatile("cp.async.wait_group 1;\n" ::: "memory")
#define CP_WAIT0()  asm volatile("cp.async.wait_group 0;\n" ::: "memory")

// ---------------------------------------------------------------------------
// Kernel 0: pre-round Wv to tf32
// ---------------------------------------------------------------------------
__global__ void cvtw_kernel(const float* __restrict__ Wv) {
    const int i = blockIdx.x * 256 + threadIdx.x;
    float4 v = ((const float4*)Wv)[i];
    v.x = to_tf32(v.x); v.y = to_tf32(v.y); v.z = to_tf32(v.z); v.w = to_tf32(v.w);
    ((float4*)g_wt)[i] = v;
}

// ---------------------------------------------------------------------------
// Kernel 1: LayerNorm — warp per row, 8 rows per CTA, no block barrier.
// ---------------------------------------------------------------------------
__global__ void __launch_bounds__(256)
ln_kernel(const float* __restrict__ x,
          const float* __restrict__ gamma,
          const float* __restrict__ beta) {
    const int wid  = threadIdx.x >> 5;
    const int lane = threadIdx.x & 31;
    const int row  = blockIdx.x * 8 + wid;

    const float4* xr = (const float4*)(x + (size_t)row * D);
    float4 v[8];
    float s = 0.f, ss = 0.f;
    #pragma unroll
    for (int i = 0; i < 8; i++) {
        v[i] = xr[i * 32 + lane];
        s  += v[i].x + v[i].y + v[i].z + v[i].w;
        ss += v[i].x * v[i].x + v[i].y * v[i].y + v[i].z * v[i].z + v[i].w * v[i].w;
    }
    #pragma unroll
    for (int o = 16; o > 0; o >>= 1) {
        s  += __shfl_xor_sync(0xFFFFFFFFu, s,  o);
        ss += __shfl_xor_sync(0xFFFFFFFFu, ss, o);
    }
    const float mu   = s * (1.0f / D);
    const float var  = ss * (1.0f / D) - mu * mu;
    const float rstd = rsqrtf(var + LN_EPS);

    float4* hr = (float4*)(g_h + (size_t)row * D);
    const float4* g4 = (const float4*)gamma;
    const float4* b4 = (const float4*)beta;
    #pragma unroll
    for (int i = 0; i < 8; i++) {
        const float4 g  = g4[i * 32 + lane];
        const float4 be = b4[i * 32 + lane];
        float4 h;
        h.x = to_tf32((v[i].x - mu) * rstd * g.x + be.x);
        h.y = to_tf32((v[i].y - mu) * rstd * g.y + be.y);
        h.z = to_tf32((v[i].z - mu) * rstd * g.z + be.z);
        h.w = to_tf32((v[i].w - mu) * rstd * g.w + be.w);
        hr[i * 32 + lane] = h;
    }
}

// ---------------------------------------------------------------------------
// Kernel 2a: Wv GEMM — cp.async 4-stage pipeline + ldmatrix fragments,
// 2 CTAs/SM. (Round-7 configuration with fixed tail waits.)
// ---------------------------------------------------------------------------
#define PBM 128
#define PBK 16
#define PST 20
#define NSTG 4
#define GEMMWV_SMEM (NSTG * 2 * PBM * PST * 4)   // 81920 B

__global__ void __launch_bounds__(256, 2)
gemm_wv_kernel(const float* __restrict__ A,
               const float* __restrict__ Wt,
               const float* __restrict__ bias,
               float* __restrict__ C) {
    extern __shared__ float smp[];
    const int m0 = blockIdx.x * PBM;
    const int n0 = blockIdx.y * PBM;

    const int tid  = threadIdx.x;
    const int wid  = tid >> 5;
    const int lane = tid & 31;
    const int wm   = wid & 3;
    const int wn   = wid >> 2;
    const int t    = lane & 3;

    const int rowA = tid >> 1;
    const int offA = (tid & 1) * 8;

    auto issue_stage = [&](int stg, int k0) {
        float* base = smp + stg * (2 * PBM * PST);
        float* bA = base;
        float* bW = base + PBM * PST;
        const float* srcA = &A[(size_t)(m0 + rowA) * 1024 + k0 + offA];
        const float* srcW = &Wt[(size_t)(n0 + rowA) * 1024 + k0 + offA];
        uint32_t dA = (uint32_t)__cvta_generic_to_shared(&bA[rowA * PST + offA]);
        uint32_t dW = (uint32_t)__cvta_generic_to_shared(&bW[rowA * PST + offA]);
        cp_async16(dA, srcA);
        cp_async16(dA + 16, srcA + 4);
        cp_async16(dW, srcW);
        cp_async16(dW + 16, srcW + 4);
        CP_COMMIT();
    };

    const int ltile = lane >> 3;
    const int lj    = lane & 7;
    uint32_t aoff[2], boff[4];
    #pragma unroll
    for (int tm = 0; tm < 2; tm++) {
        const int arow = wm * 32 + tm * 16 + (ltile & 1) * 8 + lj;
        const int acol = (ltile >> 1) * 4;
        aoff[tm] = (uint32_t)((arow * PST + acol) * 4);
    }
    #pragma unroll
    for (int gi = 0; gi < 4; gi++) {
        const int brow = wn * 64 + (gi * 2 + (ltile >> 1)) * 8 + lj;
        const int bcol = (ltile & 1) * 4;
        boff[gi] = (uint32_t)((PBM * PST + brow * PST + bcol) * 4);
    }
    const uint32_t sbase = (uint32_t)__cvta_generic_to_shared(smp);

    float acc[2][8][4];
    #pragma unroll
    for (int i = 0; i < 2; i++)
        #pragma unroll
        for (int j = 0; j < 8; j++)
            #pragma unroll
            for (int l = 0; l < 4; l++) acc[i][j][l] = 0.f;

    #pragma unroll
    for (int s = 0; s < NSTG - 1; s++) issue_stage(s, s * PBK);

    const int NIT = 1024 / PBK;   // 64
    for (int it = 0; it < NIT; it++) {
        if (it < NIT - 2)       { CP_WAIT2(); }
        else if (it == NIT - 2) { CP_WAIT1(); }
        else                    { CP_WAIT0(); }
        __syncthreads();

        const uint32_t stg = sbase + (uint32_t)((it & (NSTG - 1)) * (2 * PBM * PST) * 4);

        #pragma unroll
        for (int ks = 0; ks < 2; ks++) {
            const uint32_t kboff = (uint32_t)(ks * 8 * 4);
            uint32_t af[2][4];
            ldm_x4(af[0][0], af[0][1], af[0][2], af[0][3], stg + aoff[0] + kboff);
            ldm_x4(af[1][0], af[1][1], af[1][2], af[1][3], stg + aoff[1] + kboff);
            uint32_t bf[8][2];
            #pragma unroll
            for (int gi = 0; gi < 4; gi++) {
                ldm_x4(bf[gi * 2][0], bf[gi * 2][1],
                       bf[gi * 2 + 1][0], bf[gi * 2 + 1][1],
                       stg + boff[gi] + kboff);
            }
            #pragma unroll
            for (int tn = 0; tn < 8; tn++) {
                mma_m16n8k8_tf32(acc[0][tn], af[0], bf[tn][0], bf[tn][1]);
                mma_m16n8k8_tf32(acc[1][tn], af[1], bf[tn][0], bf[tn][1]);
            }
        }

        if (it + NSTG - 1 < NIT)
            issue_stage((it + NSTG - 1) & (NSTG - 1), (it + NSTG - 1) * PBK);
    }

    const int g = lane >> 2;
    #pragma unroll
    for (int tm = 0; tm < 2; tm++) {
        #pragma unroll
        for (int tn = 0; tn < 8; tn++) {
            const int gc   = n0 + wn * 64 + tn * 8 + 2 * t;
            const int row0 = m0 + wm * 32 + tm * 16 + g;
            const float bx = bias[gc];
            const float by = bias[gc + 1];
            float2 o0 = make_float2(acc[tm][tn][0] + bx, acc[tm][tn][1] + by);
            float2 o1 = make_float2(acc[tm][tn][2] + bx, acc[tm][tn][3] + by);
            *(float2*)&C[(size_t)row0 * D + gc] = o0;
            *(float2*)&C[(size_t)(row0 + 8) * D + gc] = o1;
        }
    }
}

// ---------------------------------------------------------------------------
// Kernel 2b: KQ GEMM — emits tf32-rounded k/q
// ---------------------------------------------------------------------------
#define GBM 128
#define GBK 16
#define SST 20
#define GK  1024

__global__ void __launch_bounds__(256, 1)
gemm_kq_kernel(const float* __restrict__ A,
               const float* __restrict__ W0,
               const float* __restrict__ W1,
               const float* __restrict__ bias0,
               const float* __restrict__ bias1,
               float* __restrict__ C0,
               float* __restrict__ C1) {
    __shared__ float sA[2][GBM * SST];
    __shared__ float sW[2][GBM * SST];

    const int tid  = threadIdx.x;
    const int m0   = blockIdx.x * GBM;
    const int wid  = tid >> 5;
    const int lane = tid & 31;
    const int wm   = wid & 3;
    const int wn   = wid >> 2;
    const int g    = lane >> 2;
    const int t    = lane & 3;
    const int lrow0 = tid >> 2;
    const int lcol  = (tid & 3) * 4;
    const int lrow1 = (tid + 256) >> 2;

    float4 aR[2], wR[2];
    auto load_tile = [&](int kk) {
        aR[0] = *(const float4*)&A[(size_t)(m0 + lrow0) * GK + kk + lcol];
        aR[1] = *(const float4*)&A[(size_t)(m0 + lrow1) * GK + kk + lcol];
        wR[0] = (lrow0 < 64)
            ? *(const float4*)&W0[(size_t)lrow0 * GK + kk + lcol]
            : *(const float4*)&W1[(size_t)(lrow0 - 64) * GK + kk + lcol];
        wR[1] = (lrow1 < 64)
            ? *(const float4*)&W0[(size_t)lrow1 * GK + kk + lcol]
            : *(const float4*)&W1[(size_t)(lrow1 - 64) * GK + kk + lcol];
    };
    auto store_tile = [&](int buf) {
        float4 a0 = aR[0], a1 = aR[1], w0 = wR[0], w1 = wR[1];
        w0.x = to_tf32(w0.x); w0.y = to_tf32(w0.y); w0.z = to_tf32(w0.z); w0.w = to_tf32(w0.w);
        w1.x = to_tf32(w1.x); w1.y = to_tf32(w1.y); w1.z = to_tf32(w1.z); w1.w = to_tf32(w1.w);
        *(float4*)&sA[buf][lrow0 * SST + lcol] = a0;
        *(float4*)&sA[buf][lrow1 * SST + lcol] = a1;
        *(float4*)&sW[buf][lrow0 * SST + lcol] = w0;
        *(float4*)&sW[buf][lrow1 * SST + lcol] = w1;
    };

    float acc[2][8][4];
    #pragma unroll
    for (int i = 0; i < 2; i++)
        #pragma unroll
        for (int j = 0; j < 8; j++)
            #pragma unroll
            for (int l = 0; l < 4; l++) acc[i][j][l] = 0.f;

    load_tile(0);
    store_tile(0);
    __syncthreads();

    const int NIT = GK / GBK;
    for (int it = 0; it < NIT; it++) {
        const int cur = it & 1;
        if (it + 1 < NIT) load_tile((it + 1) * GBK);
        #pragma unroll
        for (int ks = 0; ks < 2; ks++) {
            const int kb = ks * 8;
            uint32_t af[2][4];
            #pragma unroll
            for (int tm = 0; tm < 2; tm++) {
                const int r = wm * 32 + tm * 16 + g;
                af[tm][0] = __float_as_uint(sA[cur][r * SST + kb + t]);
                af[tm][1] = __float_as_uint(sA[cur][(r + 8) * SST + kb + t]);
                af[tm][2] = __float_as_uint(sA[cur][r * SST + kb + t + 4]);
                af[tm][3] = __float_as_uint(sA[cur][(r + 8) * SST + kb + t + 4]);
            }
            #pragma unroll
            for (int tn = 0; tn < 8; tn++) {
                const int n = wn * 64 + tn * 8 + g;
                const uint32_t b0 = __float_as_uint(sW[cur][n * SST + kb + t]);
                const uint32_t b1 = __float_as_uint(sW[cur][n * SST + kb + t + 4]);
                mma_m16n8k8_tf32(acc[0][tn], af[0], b0, b1);
                mma_m16n8k8_tf32(acc[1][tn], af[1], b0, b1);
            }
        }
        if (it + 1 < NIT) store_tile(cur ^ 1);
        __syncthreads();
    }

    #pragma unroll
    for (int tm = 0; tm < 2; tm++) {
        #pragma unroll
        for (int tn = 0; tn < 8; tn++) {
            const int colL = wn * 64 + tn * 8 + 2 * t;
            const int row0 = m0 + wm * 32 + tm * 16 + g;
            float* Cp = (colL < 64) ? C0 : C1;
            const int cc = colL & 63;
            const float bx = (colL < 64) ? bias0[cc] : bias1[cc];
            const float by = (colL < 64) ? bias0[cc + 1] : bias1[cc + 1];
            float2 o0 = make_float2(to_tf32(acc[tm][tn][0] + bx), to_tf32(acc[tm][tn][1] + by));
            float2 o1 = make_float2(to_tf32(acc[tm][tn][2] + bx), to_tf32(acc[tm][tn][3] + by));
            *(float2*)&Cp[(size_t)row0 * DS + cc] = o0;
            *(float2*)&Cp[(size_t)(row0 + 8) * DS + cc] = o1;
        }
    }
}

// ---------------------------------------------------------------------------
// Kernel 3: per-(b,chunk) precompute — emits tf32-rounded T / Bq
// ---------------------------------------------------------------------------
#define PREP_SMEM (4 * 64 * 68 * 4)

__global__ void __launch_bounds__(256)
prep_kernel() {
    extern __shared__ float sm[];
    float* sK = sm;
    float* sQ = sK + 64 * 68;
    float* sA = sQ + 64 * 68;
    float* sT = sA + 64 * 68;

    const int c = blockIdx.x, b = blockIdx.y;
    const int tid = threadIdx.x;
    const float* kg = g_k + ((size_t)b * S + c * NC) * DS;
    const float* qg = g_q + ((size_t)b * S + c * NC) * DS;

    for (int f = tid; f < NC * DS / 4; f += 256) {
        const int r = f >> 4, c4 = (f & 15) * 4;
        *(float4*)&sK[r * 68 + c4] = *(const float4*)&kg[r * DS + c4];
        *(float4*)&sQ[r * 68 + c4] = *(const float4*)&qg[r * DS + c4];
    }
    __syncthreads();

    float* Bg = g_Bq + ((size_t)(b * NCH + c)) * NC * NC;
    for (int e = tid; e < NC * NC; e += 256) {
        const int i = e >> 6, m = e & 63;
        float aK = 0.f, aQ = 0.f;
        #pragma unroll
        for (int kk = 0; kk < DS; kk += 4) {
            const float4 ki = *(const float4*)&sK[i * 68 + kk];
            const float4 qi = *(const float4*)&sQ[i * 68 + kk];
            const float4 km = *(const float4*)&sK[m * 68 + kk];
            aK += ki.x * km.x + ki.y * km.y + ki.z * km.z + ki.w * km.w;
            aQ += qi.x * km.x + qi.y * km.y + qi.z * km.z + qi.w * km.w;
        }
        sA[i * 68 + m] = (m < i) ? TTT_LR * aK : 0.f;
        Bg[e]          = (m < i) ? to_tf32(-TTT_LR * aQ) : 0.f;
    }
    __syncthreads();

    const int j = tid;
    if (j < NC) {
        for (int m = 0; m < NC; m++) sT[m * 68 + j] = (m == j) ? 1.f : 0.f;
    }
    __syncthreads();
    for (int i = 1; i < NC; i++) {
        if (j < i) {
            float s = 0.f;
            for (int m = 0; m < i; m++) s += sA[i * 68 + m] * sT[m * 68 + j];
            sT[i * 68 + j] = -s;
        }
        __syncthreads();
    }

    float* Tg = g_T + ((size_t)(b * NCH + c)) * NC * NC;
    for (int e = tid; e < NC * NC; e += 256)
        Tg[e] = to_tf32(sT[(e >> 6) * 68 + (e & 63)]);
}

// ---------------------------------------------------------------------------
// Kernel 4 (pass A): sequential state recurrence with cp.async double-buffer
// prefetch (all inputs pre-tf32). 128 CTAs.  (Round-7 configuration.)
// ---------------------------------------------------------------------------
#define CHUNK_FLTS (2 * 64 * 68 + 64 * 36)     // K + T + RV = 11008
#define SCANA_SMEM ((2 * 32 * 68 + 2 * CHUNK_FLTS + 64 * 36) * 4)

__global__ void __launch_bounds__(256, 1)
scan_state_kernel() {
    extern __shared__ float sm[];
    float* sW   = sm;                     // 32 x 68 fp32 master
    float* sWt  = sW + 32 * 68;           // 32 x 68 tf32 shadow
    float* sStg = sWt + 32 * 68;          // 2 x [K | T | RV]
    float* sU   = sStg + 2 * CHUNK_FLTS;  // 64 x 36 tf32

    const int b  = blockIdx.y;
    const int d0 = blockIdx.x * DSLA;
    const int tid  = threadIdx.x;
    const int wid  = tid >> 5;
    const int lane = tid & 31;
    const int g = lane >> 2, t = lane & 3;
    const int wm  = wid & 3;
    const int wn4 = wid >> 2;
    const int mb  = wm * 16, nb = wn4 * 16;
    const int wm2 = wid & 1;
    const int wn2 = wid >> 1;
    const int mb2 = wm2 * 16, nb2 = wn2 * 16;

    for (int i = tid; i < 32 * 68; i += 256) { sW[i] = 0.f; sWt[i] = 0.f; }

    auto stage_chunk = [&](int c, int buf) {
        float* bK  = sStg + buf * CHUNK_FLTS;
        float* bT  = bK + 64 * 68;
        float* bRV = bT + 64 * 68;
        const float* kg = g_k + ((size_t)b * S + c * NC) * DS;
        const float* Tg = g_T + ((size_t)(b * NCH + c)) * NC * NC;
        #pragma unroll
        for (int f = tid; f < 1024; f += 256) {
            const int r = f >> 4, c4 = (f & 15) * 4;
            cp_async16((uint32_t)__cvta_generic_to_shared(&bK[r * 68 + c4]),
                       &kg[r * DS + c4]);
            cp_async16((uint32_t)__cvta_generic_to_shared(&bT[r * 68 + c4]),
                       &Tg[r * 64 + c4]);
        }
        #pragma unroll
        for (int f = tid; f < 512; f += 256) {
            const int r = f >> 3, c4 = (f & 7) * 4;
            cp_async16((uint32_t)__cvta_generic_to_shared(&bRV[r * 36 + c4]),
                       &g_v[((size_t)(b * S) + c * NC + r) * D + d0 + c4]);
        }
        CP_COMMIT();
    };

    stage_chunk(0, 0);
    int buf = 0;

    for (int c = 0; c < NCH; c++) {
        if (c + 1 < NCH) { stage_chunk(c + 1, buf ^ 1); CP_WAIT1(); }
        else             { CP_WAIT0(); }
        __syncthreads();

        float* bK  = sStg + buf * CHUNK_FLTS;
        float* bT  = bK + 64 * 68;
        float* bRV = bT + 64 * 68;

        // snapshot W (tf32 shadow) -> g_w
        #pragma unroll
        for (int f = tid; f < DSLA * DS / 4; f += 256) {
            const int dd = f >> 4, s4 = (f & 15) * 4;
            *(float4*)&g_w[((size_t)(b * NCH + c) * D + d0 + dd) * DS + s4] =
                *(const float4*)&sWt[dd * 68 + s4];
        }

        // GEMM1: R = K W^T - V
        {
            float acc[2][4] = {};
            #pragma unroll
            for (int ks = 0; ks < 8; ks++) {
                const int k0 = ks * 8;
                uint32_t a[4];
                a[0] = __float_as_uint(bK[(mb + g) * 68 + k0 + t]);
                a[1] = __float_as_uint(bK[(mb + g + 8) * 68 + k0 + t]);
                a[2] = __float_as_uint(bK[(mb + g) * 68 + k0 + t + 4]);
                a[3] = __float_as_uint(bK[(mb + g + 8) * 68 + k0 + t + 4]);
                #pragma unroll
                for (int tn = 0; tn < 2; tn++) {
                    const int n = nb + tn * 8 + g;
                    const uint32_t b0 = __float_as_uint(sWt[n * 68 + k0 + t]);
                    const uint32_t b1 = __float_as_uint(sWt[n * 68 + k0 + t + 4]);
                    mma_m16n8k8_tf32(acc[tn], a, b0, b1);
                }
            }
            #pragma unroll
            for (int tn = 0; tn < 2; tn++) {
                const int cc = nb + tn * 8 + 2 * t;
                float2 v0 = *(float2*)&bRV[(mb + g) * 36 + cc];
                float2 v1 = *(float2*)&bRV[(mb + g + 8) * 36 + cc];
                *(float2*)&bRV[(mb + g) * 36 + cc] =
                    make_float2(acc[tn][0] - v0.x, acc[tn][1] - v0.y);
                *(float2*)&bRV[(mb + g + 8) * 36 + cc] =
                    make_float2(acc[tn][2] - v1.x, acc[tn][3] - v1.y);
            }
        }
        __syncthreads();

        // GEMM2: U = T R
        {
            float acc[2][4] = {};
            #pragma unroll
            for (int ks = 0; ks < 8; ks++) {
                const int k0 = ks * 8;
                uint32_t a[4];
                a[0] = __float_as_uint(bT[(mb + g) * 68 + k0 + t]);
                a[1] = __float_as_uint(bT[(mb + g + 8) * 68 + k0 + t]);
                a[2] = __float_as_uint(bT[(mb + g) * 68 + k0 + t + 4]);
                a[3] = __float_as_uint(bT[(mb + g + 8) * 68 + k0 + t + 4]);
                #pragma unroll
                for (int tn = 0; tn < 2; tn++) {
                    const int n = nb + tn * 8 + g;
                    const uint32_t b0 = __float_as_uint(to_tf32(bRV[(k0 + t) * 36 + n]));
                    const uint32_t b1 = __float_as_uint(to_tf32(bRV[(k0 + t + 4) * 36 + n]));
                    mma_m16n8k8_tf32(acc[tn], a, b0, b1);
                }
            }
            #pragma unroll
            for (int tn = 0; tn < 2; tn++) {
                const int cc = nb + tn * 8 + 2 * t;
                float2 u0 = make_float2(to_tf32(acc[tn][0]), to_tf32(acc[tn][1]));
                float2 u1 = make_float2(to_tf32(acc[tn][2]), to_tf32(acc[tn][3]));
                *(float2*)&sU[(mb + g) * 36 + cc]     = u0;
                *(float2*)&sU[(mb + g + 8) * 36 + cc] = u1;
                *(float2*)&g_u[((size_t)(b * NCH + c) * NC + mb + g) * D + d0 + cc]     = u0;
                *(float2*)&g_u[((size_t)(b * NCH + c) * NC + mb + g + 8) * D + d0 + cc] = u1;
            }
        }
        __syncthreads();

        // GEMM4: dW = U^T K + W update
        {
            float acc4[2][4] = {};
            #pragma unroll
            for (int ks = 0; ks < 8; ks++) {
                const int k0 = ks * 8;
                uint32_t a[4];
                a[0] = __float_as_uint(sU[(k0 + t) * 36 + mb2 + g]);
                a[1] = __float_as_uint(sU[(k0 + t) * 36 + mb2 + g + 8]);
                a[2] = __float_as_uint(sU[(k0 + t + 4) * 36 + mb2 + g]);
                a[3] = __float_as_uint(sU[(k0 + t + 4) * 36 + mb2 + g + 8]);
                #pragma unroll
                for (int tn = 0; tn < 2; tn++) {
                    const int n = nb2 + tn * 8 + g;
                    const uint32_t b0 = __float_as_uint(bK[(k0 + t) * 68 + n]);
                    const uint32_t b1 = __float_as_uint(bK[(k0 + t + 4) * 68 + n]);
                    mma_m16n8k8_tf32(acc4[tn], a, b0, b1);
                }
            }
            #pragma unroll
            for (int tn = 0; tn < 2; tn++) {
                const int ss = nb2 + tn * 8 + 2 * t;
                float2 w0 = *(float2*)&sW[(mb2 + g) * 68 + ss];
                float2 w1 = *(float2*)&sW[(mb2 + g + 8) * 68 + ss];
                w0.x -= TTT_LR * acc4[tn][0]; w0.y -= TTT_LR * acc4[tn][1];
                w1.x -= TTT_LR * acc4[tn][2]; w1.y -= TTT_LR * acc4[tn][3];
                *(float2*)&sW[(mb2 + g) * 68 + ss] = w0;
                *(float2*)&sW[(mb2 + g + 8) * 68 + ss] = w1;
                *(float2*)&sWt[(mb2 + g) * 68 + ss] =
                    make_float2(to_tf32(w0.x), to_tf32(w0.y));
                *(float2*)&sWt[(mb2 + g + 8) * 68 + ss] =
                    make_float2(to_tf32(w1.x), to_tf32(w1.y));
            }
        }
        __syncthreads();
        buf ^= 1;
    }
}

// ---------------------------------------------------------------------------
// Kernel 5 (pass B): fully parallel output computation — THE ONE CHANGE:
// occupancy 2 (2 CTAs/SM; smem 2x103424 = 206848 B fits 228KB carveout).
// ---------------------------------------------------------------------------
#define SCANB_SMEM ((2 * 64 * 68 + 128 * 68 + 64 * 132) * 4)

__global__ void __launch_bounds__(256, 2)
scan_y_kernel(const float* __restrict__ x, float* __restrict__ out) {
    extern __shared__ float sm[];
    float* sQ = sm;
    float* sB = sQ + 64 * 68;
    float* sW = sB + 64 * 68;
    float* sU = sW + 128 * 68;

    const int b  = blockIdx.z;
    const int c  = blockIdx.y;
    const int d0 = blockIdx.x * DSLB;
    const int t0 = c * NC;
    const int tid  = threadIdx.x;
    const int wid  = tid >> 5;
    const int lane = tid & 31;
    const int g = lane >> 2, t = lane & 3;
    const int wm = wid & 3, wn = wid >> 2;
    const int mb = wm * 16, nbv = wn * 64;

    const float* qg = g_q  + ((size_t)b * S + t0) * DS;
    const float* Bg = g_Bq + ((size_t)(b * NCH + c)) * NC * NC;
    #pragma unroll
    for (int f = tid; f < NC * DS / 4; f += 256) {
        const int r = f >> 4, c4 = (f & 15) * 4;
        *(float4*)&sQ[r * 68 + c4] = *(const float4*)&qg[r * DS + c4];
        *(float4*)&sB[r * 68 + c4] = *(const float4*)&Bg[r * 64 + c4];
    }
    const float* wg = g_w + ((size_t)(b * NCH + c) * D + d0) * DS;
    #pragma unroll
    for (int f = tid; f < DSLB * DS / 4; f += 256) {
        const int r = f >> 4, c4 = (f & 15) * 4;
        *(float4*)&sW[r * 68 + c4] = *(const float4*)&wg[(size_t)r * DS + c4];
    }
    const float* ug = g_u + ((size_t)(b * NCH + c)) * NC * D + d0;
    #pragma unroll
    for (int f = tid; f < NC * DSLB / 4; f += 256) {
        const int r = f >> 5, c4 = (f & 31) * 4;
        *(float4*)&sU[r * 132 + c4] = *(const float4*)&ug[(size_t)r * D + c4];
    }
    __syncthreads();

    float acc[8][4] = {};
    #pragma unroll
    for (int ks = 0; ks < 8; ks++) {
        const int k0 = ks * 8;
        uint32_t a[4];
        a[0] = __float_as_uint(sQ[(mb + g) * 68 + k0 + t]);
        a[1] = __float_as_uint(sQ[(mb + g + 8) * 68 + k0 + t]);
        a[2] = __float_as_uint(sQ[(mb + g) * 68 + k0 + t + 4]);
        a[3] = __float_as_uint(sQ[(mb + g + 8) * 68 + k0 + t + 4]);
        #pragma unroll
        for (int tn = 0; tn < 8; tn++) {
            const int n = nbv + tn * 8 + g;
            const uint32_t b0 = __float_as_uint(sW[n * 68 + k0 + t]);
            const uint32_t b1 = __float_as_uint(sW[n * 68 + k0 + t + 4]);
            mma_m16n8k8_tf32(acc[tn], a, b0, b1);
        }
    }
    #pragma unroll
    for (int ks = 0; ks < 8; ks++) {
        const int k0 = ks * 8;
        uint32_t a[4];
        a[0] = __float_as_uint(sB[(mb + g) * 68 + k0 + t]);
        a[1] = __float_as_uint(sB[(mb + g + 8) * 68 + k0 + t]);
        a[2] = __float_as_uint(sB[(mb + g) * 68 + k0 + t + 4]);
        a[3] = __float_as_uint(sB[(mb + g + 8) * 68 + k0 + t + 4]);
        #pragma unroll
        for (int tn = 0; tn < 8; tn++) {
            const int n = nbv + tn * 8 + g;
            const uint32_t b0 = __float_as_uint(sU[(k0 + t) * 132 + n]);
            const uint32_t b1 = __float_as_uint(sU[(k0 + t + 4) * 132 + n]);
            mma_m16n8k8_tf32(acc[tn], a, b0, b1);
        }
    }
    #pragma unroll
    for (int tn = 0; tn < 8; tn++) {
        const int dc = d0 + nbv + tn * 8 + 2 * t;
        const size_t o0 = ((size_t)b * S + t0 + mb + g) * D + dc;
        const size_t o1 = ((size_t)b * S + t0 + mb + g + 8) * D + dc;
        const float2 x0 = *(const float2*)&x[o0];
        const float2 x1 = *(const float2*)&x[o1];
        *(float2*)&out[o0] = make_float2(x0.x + acc[tn][0], x0.y + acc[tn][1]);
        *(float2*)&out[o1] = make_float2(x1.x + acc[tn][2], x1.y + acc[tn][3]);
    }
}

// ---------------------------------------------------------------------------
// Launch (round-7/15 schedule: Wv GEMM on s1 overlaps KQ + prep on main)
// ---------------------------------------------------------------------------
extern "C" void kernel_launch(void* const* d_in, const int* in_sizes, int n_in,
                              void* d_out, int out_size) {
    const float* x     = (const float*)d_in[0];
    const float* Wk    = (const float*)d_in[1];
    const float* bk    = (const float*)d_in[2];
    const float* Wv    = (const float*)d_in[3];
    const float* bv    = (const float*)d_in[4];
    const float* Wq    = (const float*)d_in[5];
    const float* bq    = (const float*)d_in[6];
    const float* gamma = (const float*)d_in[7];
    const float* beta  = (const float*)d_in[8];
    float* out = (float*)d_out;

    float* hptr;  cudaGetSymbolAddress((void**)&hptr, g_h);
    float* wtptr; cudaGetSymbolAddress((void**)&wtptr, g_wt);
    float* vptr;  cudaGetSymbolAddress((void**)&vptr, g_v);
    float* kptr;  cudaGetSymbolAddress((void**)&kptr, g_k);
    float* qptr;  cudaGetSymbolAddress((void**)&qptr, g_q);

    static cudaStream_t s1 = nullptr;
    static cudaEvent_t ev0 = nullptr, evLN = nullptr, evWv = nullptr;
    static bool attrs_set = false;
    if (!s1) {
        cudaStreamCreateWithFlags(&s1, cudaStreamNonBlocking);
        cudaEventCreateWithFlags(&ev0,  cudaEventDisableTiming);
        cudaEventCreateWithFlags(&evLN, cudaEventDisableTiming);
        cudaEventCreateWithFlags(&evWv, cudaEventDisableTiming);
    }
    if (!attrs_set) {
        cudaFuncSetAttribute(gemm_wv_kernel,
                             cudaFuncAttributeMaxDynamicSharedMemorySize, GEMMWV_SMEM);
        cudaFuncSetAttribute(prep_kernel,
                             cudaFuncAttributeMaxDynamicSharedMemorySize, PREP_SMEM);
        cudaFuncSetAttribute(scan_state_kernel,
                             cudaFuncAttributeMaxDynamicSharedMemorySize, SCANA_SMEM);
        cudaFuncSetAttribute(scan_y_kernel,
                             cudaFuncAttributeMaxDynamicSharedMemorySize, SCANB_SMEM);
        attrs_set = true;
    }

    // Fork side stream off the main (possibly capturing) stream.
    cudaEventRecord(ev0, 0);
    cudaStreamWaitEvent(s1, ev0, 0);

    // s1: pre-round Wv (independent of LN)
    cvtw_kernel<<<(D * D / 4) / 256, 256, 0, s1>>>(Wv);

    // main: LayerNorm (warp per row)
    ln_kernel<<<M_ROWS / 8, 256>>>(x, gamma, beta);
    cudaEventRecord(evLN, 0);

    // s1: Wv GEMM (needs LN + cvtw)
    cudaStreamWaitEvent(s1, evLN, 0);
    gemm_wv_kernel<<<dim3(M_ROWS / PBM, D / PBM), 256, GEMMWV_SMEM, s1>>>(
        hptr, wtptr, bv, vptr);

    // main (concurrent with Wv GEMM): KQ projection + prep
    gemm_kq_kernel<<<dim3(M_ROWS / GBM, 1), 256>>>(
        hptr, Wk, Wq, bk, bq, kptr, qptr);
    prep_kernel<<<dim3(NCH, B), 256, PREP_SMEM>>>();

    // join: scan needs g_v (s1) + g_k/g_T (main)
    cudaEventRecord(evWv, s1);
    cudaStreamWaitEvent(0, evWv, 0);

    // Pass A: sequential state recurrence (128 CTAs)
    scan_state_kernel<<<dim3(D / DSLA, B), 256, SCANA_SMEM>>>();

    // Pass B: fully parallel output computation (1024 CTAs, 2/SM)
    scan_y_kernel<<<dim3(D / DSLB, NCH, B), 256, SCANB_SMEM>>>(x, out);
}